// round 11
// baseline (speedup 1.0000x reference)
#include <cuda_runtime.h>
#include <math.h>

#define NEGV (-1e30f)

// B=8, S=512, L=32, M=64
#define B_ 8
#define S_ 512
#define L_ 32
#define M_ 64
#define SP_ (S_ + 2)          // padded frames: prefetch never needs a frame bounds check
#define RW_ 68                // scratch row stride (floats): 64 permuted j-vals + s0 + pad, 16B-aligned
#define LOG2E_ 1.4426950408889634f
#define LN2_   0.6931471805599453f

// scratch[b][e][cur][RW_]:
//   slot q (0..63): value for jm1 = (q&3)*16 + (q>>2) + 1   (so lane lp reads slots 4lp..4lp+3
//                   = jm1 in {lp+1, lp+17, lp+33, lp+49} = j in {lp+2, lp+18, lp+34, lp+50})
//   slot 64: jm1 = 0 value (s0).  slot 63 corresponds to jm1=64 (j=65, invalid) -> dummy.
__device__ float g_scratch[B_ * SP_ * L_ * RW_ + 16];

__device__ __forceinline__ float ex2f(float x) {
    float y; asm("ex2.approx.ftz.f32 %0, %1;" : "=f"(y) : "f"(x)); return y;
}
__device__ __forceinline__ float lg2f(float x) {
    float y; asm("lg2.approx.ftz.f32 %0, %1;" : "=f"(y) : "f"(x)); return y;
}
__device__ __forceinline__ float redux_max_f32(unsigned mask, float x) {
    unsigned u = __float_as_uint(x);
    unsigned k = u ^ (((unsigned)((int)u >> 31)) | 0x80000000u);      // monotone key
    unsigned r = __reduce_max_sync(mask, k);
    return __uint_as_float(r ^ ((~((unsigned)((int)r >> 31))) | 0x80000000u));
}
__device__ __forceinline__ int perm_slot(int jm1) {   // jm1 in [1,64]
    int a = jm1 - 1;
    return 4 * (a & 15) + (a >> 4);
}

// -------- pre-pass: gather band into permuted [b][e][cur][RW_] layout, log2-scaled --------
__global__ void transpose_kernel(const float* __restrict__ seg) {
    int be = blockIdx.x;
    int b = be >> 9;
    int e = be & (S_ - 1);
    __shared__ float tile[L_][M_ + 1];
    int tid = threadIdx.x;
    for (int idx = tid; idx < M_ * L_; idx += 256) {
        int jm1 = idx >> 5;
        int c   = idx & 31;
        float v = 0.0f;
        int s = e - jm1;
        if (s >= 0) v = seg[(((size_t)b * S_ + s) * S_ + e) * L_ + c] * LOG2E_;
        tile[c][jm1] = v;
    }
    __syncthreads();
    float* out = &g_scratch[((size_t)(b * SP_ + e)) * (L_ * RW_)];
    for (int idx = tid; idx < L_ * 64; idx += 256) {
        int c = idx >> 6;
        int q = idx & 63;                       // storage slot
        int jm1 = (q & 3) * 16 + (q >> 2) + 1;  // inverse perm
        out[c * RW_ + q] = (jm1 < 64) ? tile[c][jm1] : 0.0f;
    }
    for (int c = tid; c < L_; c += 256) out[c * RW_ + 64] = tile[c][0];  // s0
}

// -------- sequential recurrence: one CTA per batch, 16 warps, 2 labels per warp --------
// Half-warp (16 lanes) per label; segmented redux.sync. Beta ring is label-private.
__global__ __launch_bounds__(512, 1) void crf_kernel(const float* __restrict__ trans,
                                                     float* __restrict__ out) {
    __shared__ float2 s_alpha[2][L_];
    __shared__ float  s_beta[L_ * M_];     // [label][frame & 63]

    const int b    = blockIdx.x;
    const int tid  = threadIdx.x;
    const int w    = tid >> 5;
    const int lane = tid & 31;
    const int lp   = lane & 15;
    const int lab  = w + (lane & 16);                  // this half-warp's label
    const unsigned hm = (lane < 16) ? 0x0000FFFFu : 0xFFFF0000u;
    const bool lp0  = (lp == 0);
    const bool lp15 = (lp == 15);

    const float treg0 = trans[lp * L_ + lab] * LOG2E_ + 23.0f;          // prev = lp
    const float treg1 = trans[(lp + 16) * L_ + lab] * LOG2E_ + 23.0f;   // prev = lp+16
    const float diag  = trans[lab * L_ + lab] * LOG2E_;
    const float* seg_base = &g_scratch[((size_t)(b * SP_)) * (L_ * RW_)];
    const float* row_lab  = seg_base + (size_t)lab * RW_;
    float* ring = &s_beta[lab * M_];

    for (int i = tid; i < L_ * M_; i += 512) s_beta[i] = NEGV;
    if (tid < L_) s_alpha[0][tid] = make_float2(seg_base[(size_t)tid * RW_ + 64], 1.0f);

    // per-lane j constants: j_k = lp + 2 + 16k
    const float fj0 = (float)(lp + 2),  fj1 = (float)(lp + 18);
    const float fj2 = (float)(lp + 34), fj3 = (float)(lp + 50);
    const float d0 = diag * (float)(lp + 1),  d1 = diag * (float)(lp + 17);
    const float d2 = diag * (float)(lp + 33), d3 = diag * (float)(lp + 49);

    // Rest[1] = init segment [0,1] (j=2, slot 0 of frame-1 row); frame rows for the pipeline
    float s0_cur, Rm, Rs;
    {
        const float* r1 = row_lab + (size_t)1 * (L_ * RW_);
        s0_cur = r1[64];
        Rm = r1[0] * 2.0f + diag;      // slot 0 == jm1=1 == j=2
        Rs = 1.0f;
    }
    float4 sv4; float sinit, ns0;
    {
        const float* r2 = row_lab + (size_t)2 * (L_ * RW_);
        sv4 = *(const float4*)(r2 + 4 * lp);
        sinit = r2[4];                 // perm(jm1=2) = 4
        ns0 = r2[64];
    }
    __syncthreads();

    const float* pref = row_lab + (size_t)3 * (L_ * RW_);   // frame F+2 at F=1

#define STEP_BODY(F, PH1)                                                            \
    {                                                                                \
        /* prefetch frame F+2 bundle */                                              \
        float4 pv4 = *(const float4*)(pref + 4 * lp);                                \
        float ps0 = pref[64];                                                        \
        float pinit = 0.0f;                                                          \
        if (PH1) { if ((F) + 2 < M_) pinit = pref[perm_slot((F) + 2)]; }             \
        pref += L_ * RW_;                                                            \
                                                                                     \
        /* beta[F-1][lab] = LSE2_prev( alpha-pair + T ), 2 prev per lane */          \
        float2 ap0 = s_alpha[((F) - 1) & 1][lp];                                     \
        float2 ap1 = s_alpha[((F) - 1) & 1][lp + 16];                                \
        float Bm = redux_max_f32(hm, fmaxf(ap0.x, ap1.x));                           \
        float e0 = ex2f(ap0.x + treg0 - Bm);                                         \
        float e1 = ex2f(ap1.x + treg1 - Bm);                                         \
        unsigned bu = (unsigned)fmaf(ap0.y, e0, ap1.y * e1);                         \
        unsigned bsum = __reduce_add_sync(hm, bu);                                   \
        float beta = (Bm - 23.0f) + lg2f((float)bsum);                               \
                                                                                     \
        /* alpha[F] pair = combine(Rest[F], beta + seg(F,F)) */                      \
        float t1 = beta + s0_cur;                                                    \
        float Am = fmaxf(Rm, t1);                                                    \
        float dd = Rm - t1;                                                          \
        float ee = ex2f(0.0f - fabsf(dd));                                           \
        float As = (dd >= 0.0f) ? (Rs + ee) : fmaf(Rs, ee, 1.0f);                    \
                                                                                     \
        if (lp0) {                                                                   \
            s_alpha[(F) & 1][lab] = make_float2(Am, As);                             \
            ring[((F) - 1) & 63] = beta;                                             \
        }                                                                            \
        __syncwarp();                                                                \
                                                                                     \
        /* Rest[F+1]: 4 j's per lane (+ init at lp15/k3 in phase 1) */               \
        int ia0 = ((F) - 1 - lp) & 63;                                               \
        int ia1 = (ia0 - 16) & 63;                                                   \
        int ia2 = ia0 ^ 32;                                                          \
        int ia3 = ia1 ^ 32;                                                          \
        float t0 = ring[ia0] + fmaf(sv4.x, fj0, d0);                                 \
        float ta = ring[ia1] + fmaf(sv4.y, fj1, d1);                                 \
        float tb = ring[ia2] + fmaf(sv4.z, fj2, d2);                                 \
        float tc;                                                                    \
        if (PH1) tc = lp15 ? fmaf(sinit, (float)((F) + 2), diag * (float)((F) + 1))  \
                           : ring[ia3] + fmaf(sv4.w, fj3, d3);                       \
        else     tc = lp15 ? NEGV : ring[ia3] + fmaf(sv4.w, fj3, d3);                \
        float m2 = redux_max_f32(hm, fmaxf(fmaxf(t0, ta), fmaxf(tb, tc)));           \
        float m24 = m2 - 24.0f;                                                      \
        unsigned ru = (unsigned)((ex2f(t0 - m24) + ex2f(ta - m24)) +                 \
                                 (ex2f(tb - m24) + ex2f(tc - m24)));                 \
        unsigned rsum = __reduce_add_sync(hm, ru);                                   \
        float rsf = (float)rsum;                                                     \
        unsigned rb = __float_as_uint(rsf);                                          \
        int li = (int)(rb >> 23) - 127;                                              \
        Rm = m24 + (float)li;                                                        \
        Rs = __uint_as_float(rb - ((unsigned)li << 23));                             \
                                                                                     \
        s0_cur = ns0; sv4 = pv4; sinit = pinit; ns0 = ps0;                           \
        __syncthreads();   /* protects s_alpha: next beta read + WAR on buffers */   \
    }

    for (int f = 1; f <= 61; f += 2) { STEP_BODY(f, true) STEP_BODY(f + 1, true) }
    for (int f = 63; f < 510; f += 2) { STEP_BODY(f, false) STEP_BODY(f + 1, false) }
    STEP_BODY(511, false)
#undef STEP_BODY

    // ---- log_z = LN2 * LSE2_label ( alpha[S-1] pair ), full warp 0 ----
    if (w == 0) {
        float2 p = s_alpha[(S_ - 1) & 1][lane];
        float v = p.x + lg2f(p.y);
        float m = redux_max_f32(0xffffffffu, v);
        unsigned u = (unsigned)ex2f(v - m + 24.0f);
        unsigned s = __reduce_add_sync(0xffffffffu, u);
        if (lane == 0) out[b] = (m - 24.0f + lg2f((float)s)) * LN2_;
    }
}

extern "C" void kernel_launch(void* const* d_in, const int* in_sizes, int n_in,
                              void* d_out, int out_size) {
    const float* seg   = (const float*)d_in[0];
    const float* trans = (const float*)d_in[1];
    if (n_in >= 2 && in_sizes[0] == L_ * L_) {
        trans = (const float*)d_in[0];
        seg   = (const float*)d_in[1];
    }
    float* out = (float*)d_out;

    transpose_kernel<<<B_ * S_, 256>>>(seg);
    crf_kernel<<<B_, 512>>>(trans, out);
}

// round 13
// speedup vs baseline: 2.5741x; 2.5741x over previous
#include <cuda_runtime.h>
#include <math.h>

#define NEGV (-1e30f)

// B=8, S=512, L=32, M=64
#define B_ 8
#define S_ 512
#define L_ 32
#define M_ 64
#define SP_ (S_ + 2)          // padded frames: prefetch never needs a frame bounds check
#define LOG2E_ 1.4426950408889634f
#define LN2_   0.6931471805599453f

// scratch[b][e][cur][jm1] = segment_score[b][e-jm1][e][cur] * LOG2E  (log2 domain)
// +64 pad: unconditional row[lane+34] load overruns by <=2 floats on the last row.
__device__ float g_scratch[B_ * SP_ * L_ * M_ + 64];

__device__ __forceinline__ float ex2f(float x) {
    float y; asm("ex2.approx.ftz.f32 %0, %1;" : "=f"(y) : "f"(x)); return y;
}
__device__ __forceinline__ float lg2f(float x) {
    float y; asm("lg2.approx.ftz.f32 %0, %1;" : "=f"(y) : "f"(x)); return y;
}
__device__ __forceinline__ float redux_max_f32(float x) {
    unsigned u = __float_as_uint(x);
    unsigned k = u ^ (((unsigned)((int)u >> 31)) | 0x80000000u);      // monotone key
    unsigned r = __reduce_max_sync(0xffffffffu, k);
    return __uint_as_float(r ^ ((~((unsigned)((int)r >> 31))) | 0x80000000u));
}

// -------- pre-pass: gather band into contiguous [b][e][cur][jm1] layout, log2-scaled --------
__global__ void transpose_kernel(const float* __restrict__ seg) {
    int be = blockIdx.x;
    int b = be >> 9;
    int e = be & (S_ - 1);
    __shared__ float tile[L_][M_ + 1];
    int tid = threadIdx.x;
    for (int idx = tid; idx < M_ * L_; idx += 256) {
        int jm1 = idx >> 5;
        int c   = idx & 31;
        float v = 0.0f;
        int s = e - jm1;
        if (s >= 0) v = seg[(((size_t)b * S_ + s) * S_ + e) * L_ + c] * LOG2E_;
        tile[c][jm1] = v;
    }
    __syncthreads();
    float* out = &g_scratch[((size_t)(b * SP_ + e)) * (L_ * M_)];
    for (int idx = tid; idx < L_ * M_; idx += 256) {
        int c   = idx >> 6;
        int jm1 = idx & 63;
        out[idx] = tile[c][jm1];
    }
}

// -------- sequential recurrence: one CTA per batch, warp = cur label --------
// alpha[F] = LSE( Rest'[F] (j=3..64 + init), beta[F-2]+seg_j2*2+diag (j=2), beta[F-1]+s0 (j=1) )
// Rest'[F+1] depends only on beta[<=F-2]  -> fully off the beta critical chain; no syncwarp.
__global__ __launch_bounds__(1024, 1) void crf_kernel(const float* __restrict__ trans,
                                                      float* __restrict__ out) {
    __shared__ float2 s_alpha[2][L_];
    __shared__ float  s_beta[L_ * M_];     // [label][frame & 63], warp-private column

    const int b    = blockIdx.x;
    const int tid  = threadIdx.x;
    const int cur  = tid >> 5;
    const int lane = tid & 31;
    const bool lane0  = (lane == 0);

    const float treg23 = trans[lane * L_ + cur] * LOG2E_ + 23.0f;   // T[prev=lane][cur] + bias
    const float diag   = trans[cur * L_ + cur] * LOG2E_;
    const float* seg_base = &g_scratch[((size_t)(b * SP_)) * (L_ * M_)];
    float* ring = &s_beta[cur * M_];

    for (int i = tid; i < L_ * M_; i += 1024) s_beta[i] = NEGV;
    if (tid < L_) s_alpha[0][tid] = make_float2(seg_base[tid * M_], 1.0f);

    // Rest' lane constants: a-slot j = lane+3, b-slot j = lane+35
    const float fja = (float)(lane + 3),  fjb = (float)(lane + 35);
    const float da  = diag * (float)(lane + 2);
    const float db  = diag * (float)(lane + 34);
    const bool  bvalid = (lane < 30);     // b-slot j <= 64
    const bool  lane31 = (lane == 31);

    // preload: s01 for frame 1; sa/sb/ninit for frame 2; Rest'[1] = init segment [0,1]
    float2 s01 = *(const float2*)(seg_base + (size_t)1 * (L_ * M_) + (size_t)cur * M_);
    float Rm, Rs, beta_prev = NEGV;
    {
        Rm = s01.y * 2.0f + diag;       // row1[1] = seg(0,1): init [0,1] has j=2
        Rs = 1.0f;
    }
    float sa, sb, ninit;
    {
        const float* r2 = seg_base + (size_t)2 * (L_ * M_) + (size_t)cur * M_;
        sa = r2[lane + 2];
        sb = r2[lane + 34];             // lanes 30/31 garbage, unused
        ninit = r2[2];
    }
    __syncthreads();

    const float* pp = seg_base + (size_t)2 * (L_ * M_) + (size_t)cur * M_;  // row(F+1) at F=1

#define STEP_BODY(F, PH1)                                                            \
    {                                                                                \
        /* prefetch: s01 for frame F+1 (from pp), sa/sb/init for frame F+2 */        \
        float2 p01 = *(const float2*)pp;                                             \
        const float* pn = pp + L_ * M_;                                              \
        float psa = pn[lane + 2];                                                    \
        float psb = pn[lane + 34];                                                   \
        float pinit = 0.0f;                                                          \
        if (PH1) { if ((F) + 2 < M_) pinit = pn[(F) + 2]; }                          \
        pp = pn;                                                                     \
                                                                                     \
        /* beta[F-1][cur] = LSE2_prev( alpha-pair + T ) */                           \
        float2 ap = s_alpha[((F) - 1) & 1][lane];                                    \
        float Bm = redux_max_f32(ap.x);                                              \
        unsigned bu = (unsigned)(ap.y * ex2f(ap.x + treg23 - Bm));                   \
        unsigned bsum = __reduce_add_sync(0xffffffffu, bu);                          \
        float beta = (Bm - 23.0f) + lg2f((float)bsum);                               \
                                                                                     \
        /* alpha[F] = LSE(Rest'[F], j2 via beta_prev, j1 via beta) */                \
        float t1 = beta + s01.x;                                                     \
        float t2 = fmaf(s01.y, 2.0f, diag) + beta_prev;                              \
        float Am = fmaxf(fmaxf(Rm, t1), t2);                                         \
        float As = fmaf(Rs, ex2f(Rm - Am), ex2f(t1 - Am) + ex2f(t2 - Am));           \
                                                                                     \
        if (lane0) {                                                                 \
            s_alpha[(F) & 1][cur] = make_float2(Am, As);                             \
            ring[((F) - 1) & 63] = beta;                                             \
        }                                                                            \
        __syncthreads();                                                             \
                                                                                     \
        /* Rest'[F+1]: j=3..64 (+ init at lane31 in phase 1); needs beta[<=F-2] */   \
        int ia = ((F) - 2 - lane) & 63;                                              \
        float ta = ring[ia] + fmaf(sa, fja, da);                                     \
        float tbeta = ring[ia ^ 32];                                                 \
        float tb;                                                                    \
        if (PH1) tb = lane31 ? fmaf(ninit, (float)((F) + 2), diag * (float)((F) + 1))\
                             : (bvalid ? tbeta + fmaf(sb, fjb, db) : NEGV);          \
        else     tb = bvalid ? tbeta + fmaf(sb, fjb, db) : NEGV;                     \
        float m2 = redux_max_f32(fmaxf(ta, tb));                                     \
        float m24 = m2 - 24.0f;                                                      \
        unsigned ru = (unsigned)(ex2f(ta - m24) + ex2f(tb - m24));                   \
        unsigned rsum = __reduce_add_sync(0xffffffffu, ru);                          \
        float rsf = (float)rsum;                                                     \
        unsigned rb = __float_as_uint(rsf);                                          \
        int li = (int)(rb >> 23) - 127;                                              \
        Rm = m24 + (float)li;                                                        \
        Rs = __uint_as_float(rb - ((unsigned)li << 23));                             \
                                                                                     \
        beta_prev = beta; s01 = p01; sa = psa; sb = psb; ninit = pinit;              \
    }

    for (int f = 1; f <= 61; f += 2) { STEP_BODY(f, true) STEP_BODY(f + 1, true) }
    for (int f = 63; f < 510; f += 2) { STEP_BODY(f, false) STEP_BODY(f + 1, false) }
    STEP_BODY(511, false)
#undef STEP_BODY

    // ---- log_z = LN2 * LSE2_cur ( alpha[S-1] pair ) ----
    if (cur == 0) {
        float2 p = s_alpha[(S_ - 1) & 1][lane];
        float v = p.x + lg2f(p.y);
        float m = redux_max_f32(v);
        unsigned u = (unsigned)ex2f(v - m + 24.0f);
        unsigned s = __reduce_add_sync(0xffffffffu, u);
        if (lane == 0) out[b] = (m - 24.0f + lg2f((float)s)) * LN2_;
    }
}

extern "C" void kernel_launch(void* const* d_in, const int* in_sizes, int n_in,
                              void* d_out, int out_size) {
    const float* seg   = (const float*)d_in[0];
    const float* trans = (const float*)d_in[1];
    if (n_in >= 2 && in_sizes[0] == L_ * L_) {
        trans = (const float*)d_in[0];
        seg   = (const float*)d_in[1];
    }
    float* out = (float*)d_out;

    transpose_kernel<<<B_ * S_, 256>>>(seg);
    crf_kernel<<<B_, 1024>>>(trans, out);
}

// round 15
// speedup vs baseline: 2.9320x; 1.1390x over previous
#include <cuda_runtime.h>
#include <math.h>

// B=8, S=512, L=32, M=64
#define B_ 8
#define S_ 512
#define L_ 32
#define M_ 64
#define SP_ (S_ + 2)          // padded frames: prefetch never needs a frame bounds check
#define LOG2E_ 1.4426950408889634f
#define LN2_   0.6931471805599453f
#define SHIFT_ 512.0f         // alpha/beta live in "log2 + 512" domain: always positive floats
#define CLAMPV_ 1.0f          // shifted stand-in for -inf (real -511; contributes 2^-500 mass)

// scratch[b][e][cur][jm1] = segment_score[b][e-jm1][e][cur] * LOG2E  (log2 domain, UNSHIFTED)
// +64 pad: lane's unconditional row[lane+33] load may overrun the last row slightly.
__device__ float g_scratch[B_ * SP_ * L_ * M_ + 64];

__device__ __forceinline__ float ex2f(float x) {
    float y; asm("ex2.approx.ftz.f32 %0, %1;" : "=f"(y) : "f"(x)); return y;
}
__device__ __forceinline__ float lg2f(float x) {
    float y; asm("lg2.approx.ftz.f32 %0, %1;" : "=f"(y) : "f"(x)); return y;
}
// max over warp of POSITIVE floats: raw-bit u32 redux (monotone for positive floats)
__device__ __forceinline__ float redux_max_pos(float x) {
    return __uint_as_float(__reduce_max_sync(0xffffffffu, __float_as_uint(x)));
}

// -------- pre-pass: gather band into contiguous [b][e][cur][jm1] layout, log2-scaled --------
__global__ void transpose_kernel(const float* __restrict__ seg) {
    int be = blockIdx.x;
    int b = be >> 9;
    int e = be & (S_ - 1);
    __shared__ float tile[L_][M_ + 1];
    int tid = threadIdx.x;
    for (int idx = tid; idx < M_ * L_; idx += 256) {
        int jm1 = idx >> 5;
        int c   = idx & 31;
        float v = 0.0f;
        int s = e - jm1;
        if (s >= 0) v = seg[(((size_t)b * S_ + s) * S_ + e) * L_ + c] * LOG2E_;
        tile[c][jm1] = v;
    }
    __syncthreads();
    float* out = &g_scratch[((size_t)(b * SP_ + e)) * (L_ * M_)];
    for (int idx = tid; idx < L_ * M_; idx += 256) {
        int c   = idx >> 6;
        int jm1 = idx & 63;
        out[idx] = tile[c][jm1];
    }
}

// -------- sequential recurrence: one CTA per batch, warp = cur label --------
// alpha: unnormalized (m, s) pair (m shifted +512, s in [1,3)); beta: shifted scalar log2,
// warp-private ring [cur][frame & 63]. One __syncthreads per step.
__global__ __launch_bounds__(1024, 1) void crf_kernel(const float* __restrict__ trans,
                                                      float* __restrict__ out) {
    __shared__ float2 s_alpha[2][L_];
    __shared__ float  s_beta[L_ * M_];     // [label][frame & 63]

    const int b    = blockIdx.x;
    const int tid  = threadIdx.x;
    const int cur  = tid >> 5;
    const int lane = tid & 31;
    const bool lane0  = (lane == 0);
    const bool lane31 = (lane == 31);

    const float treg23 = trans[lane * L_ + cur] * LOG2E_ + 23.0f;   // T[prev=lane][cur] + bias
    const float diag   = trans[cur * L_ + cur] * LOG2E_;
    const float* seg_base = &g_scratch[((size_t)(b * SP_)) * (L_ * M_)];
    float* ring = &s_beta[cur * M_];

    for (int i = tid; i < L_ * M_; i += 1024) s_beta[i] = CLAMPV_;   // guards make reads safe anyway
    if (tid < L_) s_alpha[0][tid] = make_float2(seg_base[tid * M_] + SHIFT_, 1.0f);

    const float fja = (float)(lane + 2), fjb = (float)(lane + 34);
    const float da  = diag * (float)(lane + 1);
    const float db  = diag * (float)(lane + 33);

    // Rest[1] = init segment [0,1] only (shifted); frame-2 bundle
    float s0_cur, Rm, Rs;
    {
        const float* r1 = seg_base + (size_t)1 * (L_ * M_) + (size_t)cur * M_;
        s0_cur = r1[0];
        Rm = r1[1] * 2.0f + diag + SHIFT_;
        Rs = 1.0f;
    }
    float nsa, nsb, ns0, ninit;
    {
        const float* r2 = seg_base + (size_t)2 * (L_ * M_) + (size_t)cur * M_;
        nsa = r2[lane + 1];
        nsb = r2[lane + 33];          // lane31 slot unused
        ns0 = r2[0];
        ninit = r2[2];
    }
    __syncthreads();

    const float* pref = seg_base + (size_t)3 * (L_ * M_) + (size_t)cur * M_;  // frame F+2 at F=1

// PH1: init-segment + ring-validity guards active (F <= 62). Guards:
//   a-term (j=lane+2)  valid iff lane <= F-1
//   b-term (j=lane+34) valid iff lane <= F-33   (lane31 carries the init segment instead)
#define STEP_BODY(F, PH1)                                                            \
    {                                                                                \
        /* prefetch frame F+2 bundle */                                              \
        float psa = pref[lane + 1];                                                  \
        float psb = pref[lane + 33];                                                 \
        float ps0 = pref[0];                                                         \
        float pinit = 0.0f;                                                          \
        if (PH1) { if ((F) + 2 < M_) pinit = pref[(F) + 2]; }                        \
        pref += L_ * M_;                                                             \
                                                                                     \
        /* beta[F-1][cur] = LSE2_prev( alpha-pair + T ), shifted */                  \
        float2 ap = s_alpha[((F) - 1) & 1][lane];                                    \
        float Bm = redux_max_pos(ap.x);                                              \
        unsigned bu = (unsigned)(ap.y * ex2f(ap.x + treg23 - Bm));                   \
        unsigned bsum = __reduce_add_sync(0xffffffffu, bu);                          \
        float beta = (Bm - 23.0f) + lg2f((float)bsum);                               \
                                                                                     \
        /* alpha[F] pair = combine(Rest[F], beta + seg(F,F)) */                      \
        float t1 = beta + s0_cur;                                                    \
        float Am = fmaxf(Rm, t1);                                                    \
        float dd = Rm - t1;                                                          \
        float ee = ex2f(0.0f - fabsf(dd));                                           \
        float As = (dd >= 0.0f) ? (Rs + ee) : fmaf(Rs, ee, 1.0f);                    \
                                                                                     \
        if (lane0) {                                                                 \
            s_alpha[(F) & 1][cur] = make_float2(Am, As);                             \
            ring[((F) - 1) & 63] = beta;                                             \
        }                                                                            \
        __syncwarp();                                                                \
                                                                                     \
        /* Rest[F+1]: j=2..64 (+ init at lane31 in phase 1); ring warp-private */    \
        int ia = ((F) - 1 - lane) & 63;                                              \
        float ta = ring[ia] + fmaf(nsa, fja, da);                                    \
        float tbeta = ring[ia ^ 32];                                                 \
        float tb = tbeta + fmaf(nsb, fjb, db);                                       \
        if (PH1) {                                                                   \
            if (lane > (F) - 1) ta = CLAMPV_;                                        \
            tb = lane31 ? fmaf(ninit, (float)((F) + 2),                              \
                               diag * (float)((F) + 1) + SHIFT_)                     \
                        : ((lane > (F) - 33) ? CLAMPV_ : tb);                        \
        } else {                                                                     \
            if (lane31) tb = CLAMPV_;                                                \
        }                                                                            \
        ta = fmaxf(ta, CLAMPV_);   /* tail-safety: keep terms positive */            \
        tb = fmaxf(tb, CLAMPV_);                                                     \
        float m2 = redux_max_pos(fmaxf(ta, tb));                                     \
        float m24 = m2 - 24.0f;                                                      \
        unsigned ru = (unsigned)(ex2f(ta - m24) + ex2f(tb - m24));                   \
        unsigned rsum = __reduce_add_sync(0xffffffffu, ru);                          \
        float rsf = (float)rsum;                                                     \
        unsigned rb = __float_as_uint(rsf);                                          \
        int li = (int)(rb >> 23) - 127;                                              \
        Rm = m24 + (float)li;                                                        \
        Rs = __uint_as_float(rb - ((unsigned)li << 23));                             \
                                                                                     \
        s0_cur = ns0; nsa = psa; nsb = psb; ns0 = ps0; ninit = pinit;                \
        __syncthreads();   /* protects s_alpha: next beta read + WAR on buffers */   \
    }

    for (int f = 1; f <= 61; f += 2) { STEP_BODY(f, true) STEP_BODY(f + 1, true) }
    STEP_BODY(62, true)
    for (int f = 63; f < 511; f += 2) { STEP_BODY(f, false) STEP_BODY(f + 1, false) }
    STEP_BODY(511, false)
#undef STEP_BODY

    // ---- log_z = LN2 * ( LSE2_cur(alpha pair) - SHIFT ) ----
    if (cur == 0) {
        float2 p = s_alpha[(S_ - 1) & 1][lane];
        float v = p.x + lg2f(p.y);
        float m = redux_max_pos(v);
        unsigned u = (unsigned)ex2f(v - m + 24.0f);
        unsigned s = __reduce_add_sync(0xffffffffu, u);
        if (lane == 0) out[b] = (m - 24.0f - SHIFT_ + lg2f((float)s)) * LN2_;
    }
}

extern "C" void kernel_launch(void* const* d_in, const int* in_sizes, int n_in,
                              void* d_out, int out_size) {
    const float* seg   = (const float*)d_in[0];
    const float* trans = (const float*)d_in[1];
    if (n_in >= 2 && in_sizes[0] == L_ * L_) {
        trans = (const float*)d_in[0];
        seg   = (const float*)d_in[1];
    }
    float* out = (float*)d_out;

    transpose_kernel<<<B_ * S_, 256>>>(seg);
    crf_kernel<<<B_, 1024>>>(trans, out);
}